// round 10
// baseline (speedup 1.0000x reference)
#include <cuda_runtime.h>
#include <cuda_bf16.h>
#include <cuda_fp8.h>
#include <cuda_fp16.h>
#include <math.h>
#include <stdint.h>

// Problem shape (fixed)
#define T 1024
#define H 2880
#define NI 2880
#define NEXP 8
#define R1 5760          // 2*I rows of gate_up
#define G 90             // K groups of 32
#define NA 2048          // T * topk

// GEMM tile
#define BM 128
#define BN 64
#define ASTR 40          // padded row stride in bf16 elems (80 bytes)
#define ASTRB 80
#define STAGE_ELEMS ((BM + BN) * ASTR)     // 7680 bf16 per stage
#define BS_OFF (BM * ASTR)                 // Bs offset within stage (elems)

// ---------------- scratch ---------------------------------------------------
__device__ __nv_bfloat16 g_xq[T * H];      // qdq'd hidden, bf16 (exact)
__device__ float         g_act[NA * NI];   // swiglu activations fp32
__device__ __nv_bfloat16 g_actb[NA * NI];  // qdq'd activations, bf16 (exact)
__device__ float         g_out2[NA * H];   // per-assignment outputs
__device__ int g_tok[NA], g_pair_row[NA], g_cnt[NEXP], g_off[NEXP];

// ---------------- expert grouping (deterministic) ---------------------------
__global__ void build_lists_kernel(const int* __restrict__ eidx) {
    __shared__ int se[NA];
    __shared__ int offs[NEXP];
    int tid = threadIdx.x;
    for (int i = tid; i < NA; i += 256) se[i] = eidx[i];
    __syncthreads();
    if (tid < NEXP) {
        int c = 0;
        for (int i = 0; i < NA; i++) c += (se[i] == tid);
        g_cnt[tid] = c;
    }
    __syncthreads();
    if (tid == 0) {
        int s = 0;
        for (int e = 0; e < NEXP; e++) { offs[e] = s; g_off[e] = s; s += g_cnt[e]; }
    }
    __syncthreads();
    if (tid < NEXP) {
        int pos = offs[tid];
        for (int i = 0; i < NA; i++) {
            if (se[i] == tid) {
                g_tok[pos] = i >> 1;
                g_pair_row[i] = pos;
                pos++;
            }
        }
    }
}

// ---------------- MXFP8 qdq -> bf16 -----------------------------------------
__device__ __forceinline__ void qdq_block_bf16(const float* __restrict__ in,
                                               __nv_bfloat16* __restrict__ out,
                                               int nblk) {
    int w = (blockIdx.x * blockDim.x + threadIdx.x) >> 5;
    int lane = threadIdx.x & 31;
    if (w >= nblk) return;
    size_t idx = (size_t)w * 32 + lane;
    float v = in[idx];
    float a = fabsf(v);
#pragma unroll
    for (int o = 16; o; o >>= 1) a = fmaxf(a, __shfl_xor_sync(0xffffffffu, a, o));
    a = fmaxf(a, 1e-12f);
    int k; float m = frexpf(a, &k);
    int ee = (m == 0.5f) ? (k - 1) : k;     // exact ceil(log2(a))
    ee = max(-127, min(128, ee));
    float inv = ldexpf(1.0f, -ee);
    float scale = ldexpf(1.0f, ee);
    __nv_fp8_storage_t q = __nv_cvt_float_to_fp8(v * inv, __NV_SATFINITE, __NV_E4M3);
    __half_raw hr = __nv_cvt_fp8_to_halfraw(q, __NV_E4M3);
    float deq = __half2float(*(__half*)&hr);
    out[idx] = __float2bfloat16(deq * scale);   // exact: 3-bit mantissa * 2^e
}

__global__ void qdq_hidden_kernel(const float* __restrict__ hidden) {
    qdq_block_bf16(hidden, g_xq, T * G);
}
__global__ void qdq_act_kernel() {
    qdq_block_bf16(g_act, g_actb, NA * G);
}

// ---------------- low-level helpers -----------------------------------------
__device__ __forceinline__ void ldsm_x4(uint32_t* r, uint32_t addr) {
    asm volatile("ldmatrix.sync.aligned.m8n8.x4.shared.b16 {%0,%1,%2,%3}, [%4];\n"
                 : "=r"(r[0]), "=r"(r[1]), "=r"(r[2]), "=r"(r[3]) : "r"(addr));
}
__device__ __forceinline__ void mma16816(float* d, const uint32_t* a,
                                         uint32_t b0, uint32_t b1) {
    asm volatile(
        "mma.sync.aligned.m16n8k16.row.col.f32.bf16.bf16.f32 "
        "{%0,%1,%2,%3}, {%4,%5,%6,%7}, {%8,%9}, {%0,%1,%2,%3};\n"
        : "+f"(d[0]), "+f"(d[1]), "+f"(d[2]), "+f"(d[3])
        : "r"(a[0]), "r"(a[1]), "r"(a[2]), "r"(a[3]), "r"(b0), "r"(b1));
}
__device__ __forceinline__ void cp16(uint32_t dst, const void* src) {
    asm volatile("cp.async.cg.shared.global [%0], [%1], 16;\n"
                 :: "r"(dst), "l"(src));
}
__device__ __forceinline__ uint32_t mulbf2(uint32_t a, uint32_t b) {
    uint32_t d;
    asm("mul.rn.bf16x2 %0, %1, %2;\n" : "=r"(d) : "r"(a), "r"(b));
    return d;
}

// PRMT-based fp4 dequant: 4 int32 (one packed byte each: lo/hi nibble = 2 fp4
// values) + E8M0 scale -> 4 x bf16x2 in k-order (lo0,hi0),(lo1,hi1),... Exact.
// PRMT takes its four indices from the NIBBLES of sel[15:0], so the
// byte-resident 3-bit codes are nibble-packed first (y = x | x>>4).
__device__ __forceinline__ void dequant8(int4 v, int sval, uint32_t* out) {
    uint32_t c1 = __byte_perm((uint32_t)v.x, (uint32_t)v.y, 0x0040);
    uint32_t c2 = __byte_perm((uint32_t)v.z, (uint32_t)v.w, 0x4000);
    uint32_t comb = __byte_perm(c1, c2, 0x7610);   // [b(x),b(y),b(z),b(w)]
    uint32_t chn = comb >> 4;
    uint32_t xl = comb & 0x07070707u;              // lo-nibble codes (bytes)
    uint32_t xh = chn & 0x07070707u;               // hi-nibble codes (bytes)
    uint32_t sgl = (comb & 0x08080808u) << 4;      // sign -> bf16 bit15 byte
    uint32_t sgh = (chn & 0x08080808u) << 4;
    uint32_t yl = xl | (xl >> 4);                  // b0=c0|c1<<4, b2=c2|c3<<4
    uint32_t yh = xh | (xh >> 4);
    uint32_t sel_l = __byte_perm(yl, yl, 0x0020);  // sel nibbles = c0,c1,c2,c3
    uint32_t sel_h = __byte_perm(yh, yh, 0x0020);
    // bf16 magnitude byte tables for fp4 codes 0..7: {0,.5,1,1.5,2,3,4,6}
    uint32_t hbLo = __byte_perm(0x3F3F3F00u, 0x40404040u, sel_l) | sgl;
    uint32_t lbLo = __byte_perm(0xC0800000u, 0xC0804000u, sel_l);
    uint32_t hbHi = __byte_perm(0x3F3F3F00u, 0x40404040u, sel_h) | sgh;
    uint32_t lbHi = __byte_perm(0xC0800000u, 0xC0804000u, sel_h);
    uint32_t M0 = __byte_perm(lbLo, hbLo, 0x5140);  // bf16(lo0)|bf16(lo1)<<16
    uint32_t M1 = __byte_perm(lbLo, hbLo, 0x7362);
    uint32_t N0 = __byte_perm(lbHi, hbHi, 0x5140);
    uint32_t N1 = __byte_perm(lbHi, hbHi, 0x7362);
    uint32_t sb = ((uint32_t)sval) << 7;            // bf16 2^(sval-127)
    sb |= sb << 16;
    out[0] = mulbf2(__byte_perm(M0, N0, 0x5410), sb);
    out[1] = mulbf2(__byte_perm(M0, N0, 0x7632), sb);
    out[2] = mulbf2(__byte_perm(M1, N1, 0x5410), sb);
    out[3] = mulbf2(__byte_perm(M1, N1, 0x7632), sb);
}

// ---------------- tensor-core GEMM (both stages) -----------------------------
// C[128,64] per block; 8 warps of 32x32. 3-stage smem ring, cp.async A,
// register double-buffered raw B, one __syncthreads per K-group.
template <bool IS_G1>
__global__ __launch_bounds__(256, 2) void gemm_mma_kernel(
    const int* __restrict__ wblocks, const int* __restrict__ wscales,
    const float* __restrict__ wbias, int NR) {
    int e = blockIdx.z;
    int cnt = g_cnt[e];
    int m0 = blockIdx.y * BM;
    if (m0 >= cnt) return;
    int off = g_off[e];
    int nt = blockIdx.x;

    __shared__ __nv_bfloat16 ring[3 * STAGE_ELEMS];   // 46 KB
    int tid = threadIdx.x;

    // --- A mapping: 2 threads per row, 32B (16 bf16) each ---
    int a_m = tid >> 1;
    int a_half = tid & 1;
    int arow = min(m0 + a_m, cnt - 1);   // clamp; garbage rows never stored
    const __nv_bfloat16* aptr;
    if (IS_G1) {
        int tok = g_tok[off + arow];
        aptr = g_xq + (size_t)tok * H + a_half * 16;
    } else {
        aptr = g_actb + (size_t)(off + arow) * NI + a_half * 16;
    }
    // --- B mapping: 4 threads per weight row, 4 int32 (8 fp4 values) ---
    int b_n = tid >> 2;
    int b_i = tid & 3;
    int wrow = e * NR + nt * BN + b_n;
    const int* bptr = wblocks + (size_t)wrow * (G * 16) + b_i * 4;
    const int* sptr = wscales + (size_t)wrow * G;

    uint32_t ring_u = (uint32_t)__cvta_generic_to_shared(ring);
    uint32_t st_u[3] = {ring_u, ring_u + STAGE_ELEMS * 2,
                        ring_u + 2 * STAGE_ELEMS * 2};
    uint32_t a_dst_off = (uint32_t)a_m * ASTRB + a_half * 32;   // bytes
    uint32_t b_dst_off = BS_OFF * 2 + (uint32_t)b_n * ASTRB + b_i * 16;

    // per-warp ldmatrix offsets (within a stage)
    int wid = tid >> 5, lane = tid & 31;
    int wm = (wid & 3) * 32;
    int wn = (wid >> 2) * 32;
    uint32_t aA_off = (uint32_t)(wm + (lane & 15)) * ASTRB + (lane >> 4) * 16;
    uint32_t aB_off = BS_OFF * 2 + (uint32_t)(wn + (lane & 15)) * ASTRB +
                      (lane >> 4) * 16;

    float acc[2][4][4];
#pragma unroll
    for (int i = 0; i < 2; i++)
#pragma unroll
        for (int j = 0; j < 4; j++)
#pragma unroll
            for (int c = 0; c < 4; c++) acc[i][j][c] = 0.0f;

    // ---- prologue: A stages 0,1 via cp.async; B groups 0,1 into regs ----
    cp16(st_u[0] + a_dst_off, aptr);
    cp16(st_u[0] + a_dst_off + 16, aptr + 8);
    asm volatile("cp.async.commit_group;\n");
    cp16(st_u[1] + a_dst_off, aptr + 32);
    cp16(st_u[1] + a_dst_off + 16, aptr + 40);
    asm volatile("cp.async.commit_group;\n");
    int4 b_buf[2];
    int s_buf[2];
    b_buf[0] = *(const int4*)(bptr);
    s_buf[0] = sptr[0];
    b_buf[1] = *(const int4*)(bptr + 16);
    s_buf[1] = sptr[1];

    for (int g = 0; g < G; ++g) {
        int s = g % 3;
        int p = g & 1;
        // dequant + store B for group g (stage s last read 3 groups ago)
        {
            uint32_t o[4];
            dequant8(b_buf[p], s_buf[p], o);
            uint4 u = make_uint4(o[0], o[1], o[2], o[3]);
            asm volatile("st.shared.v4.b32 [%0], {%1,%2,%3,%4};\n"
                         :: "r"(st_u[s] + b_dst_off),
                            "r"(u.x), "r"(u.y), "r"(u.z), "r"(u.w));
        }
        // A(g) guaranteed landed (allow A(g+1) in flight)
        if (g == G - 1)
            asm volatile("cp.async.wait_group 0;\n");
        else
            asm volatile("cp.async.wait_group 1;\n");
        __syncthreads();
        // issue next-next loads (stage (g+2)%3 == (g-1)%3, drained by sync)
        if (g + 2 < G) {
            uint32_t d = st_u[(g + 2) % 3] + a_dst_off;
            const __nv_bfloat16* ap = aptr + (size_t)(g + 2) * 32;
            cp16(d, ap);
            cp16(d + 16, ap + 8);
            asm volatile("cp.async.commit_group;\n");
            b_buf[p] = *(const int4*)(bptr + (size_t)(g + 2) * 16);
            s_buf[p] = sptr[g + 2];
        }
        // compute group g from stage s
        uint32_t aA = st_u[s] + aA_off;
        uint32_t aB = st_u[s] + aB_off;
#pragma unroll
        for (int ss = 0; ss < 2; ss++) {
            uint32_t A0[4], A1[4], B0[4], B1[4];
            ldsm_x4(A0, aA + ss * 32);
            ldsm_x4(A1, aA + 16 * ASTRB + ss * 32);
            ldsm_x4(B0, aB + ss * 32);
            ldsm_x4(B1, aB + 16 * ASTRB + ss * 32);
            mma16816(acc[0][0], A0, B0[0], B0[2]);
            mma16816(acc[0][1], A0, B0[1], B0[3]);
            mma16816(acc[0][2], A0, B1[0], B1[2]);
            mma16816(acc[0][3], A0, B1[1], B1[3]);
            mma16816(acc[1][0], A1, B0[0], B0[2]);
            mma16816(acc[1][1], A1, B0[1], B0[3]);
            mma16816(acc[1][2], A1, B1[0], B1[2]);
            mma16816(acc[1][3], A1, B1[1], B1[3]);
        }
    }

    // ---------------- epilogue ----------------
    int lm = lane >> 2;
    int lc = (lane & 3) * 2;
#pragma unroll
    for (int ms = 0; ms < 2; ms++) {
#pragma unroll
        for (int nf = 0; nf < 4; nf++) {
            int col = nt * BN + wn + nf * 8 + lc;
            int rbase = m0 + wm + ms * 16 + lm;
            float c0 = acc[ms][nf][0], c1 = acc[ms][nf][1];
            float c2 = acc[ms][nf][2], c3 = acc[ms][nf][3];
            if (IS_G1) {
                float be = wbias[e * R1 + col];
                float bo = wbias[e * R1 + col + 1];
                int j = col >> 1;
                if (rbase < cnt) {
                    float gate = fminf(c0 + be, 7.0f);
                    float up = fminf(fmaxf(c1 + bo, -7.0f), 7.0f);
                    float glu = gate / (1.0f + expf(-1.702f * gate));
                    g_act[(size_t)(off + rbase) * NI + j] = (up + 1.0f) * glu;
                }
                if (rbase + 8 < cnt) {
                    float gate = fminf(c2 + be, 7.0f);
                    float up = fminf(fmaxf(c3 + bo, -7.0f), 7.0f);
                    float glu = gate / (1.0f + expf(-1.702f * gate));
                    g_act[(size_t)(off + rbase + 8) * NI + j] = (up + 1.0f) * glu;
                }
            } else {
                float b0 = wbias[e * H + col];
                float b1 = wbias[e * H + col + 1];
                if (rbase < cnt) {
                    float2 r = make_float2(c0 + b0, c1 + b1);
                    *(float2*)(g_out2 + (size_t)(off + rbase) * H + col) = r;
                }
                if (rbase + 8 < cnt) {
                    float2 r = make_float2(c2 + b0, c3 + b1);
                    *(float2*)(g_out2 + (size_t)(off + rbase + 8) * H + col) = r;
                }
            }
        }
    }
}

// ---------------- combine (deterministic) -----------------------------------
__global__ void combine_kernel(const float* __restrict__ rw,
                               float* __restrict__ out) {
    int t = blockIdx.x;
    int r0 = g_pair_row[t * 2 + 0];
    int r1 = g_pair_row[t * 2 + 1];
    float w0 = rw[t * 2 + 0];
    float w1 = rw[t * 2 + 1];
    const float* p0 = g_out2 + (size_t)r0 * H;
    const float* p1 = g_out2 + (size_t)r1 * H;
    float* po = out + (size_t)t * H;
    for (int n = threadIdx.x; n < H; n += blockDim.x)
        po[n] = w0 * p0[n] + w1 * p1[n];
}

// ---------------- launch ------------------------------------------------------
extern "C" void kernel_launch(void* const* d_in, const int* in_sizes, int n_in,
                              void* d_out, int out_size) {
    const float* hidden = (const float*)d_in[0];
    const int*   eidx   = (const int*)d_in[1];
    const float* rw     = (const float*)d_in[2];
    const int*   gub    = (const int*)d_in[3];
    const int*   gus    = (const int*)d_in[4];
    const float* gubias = (const float*)d_in[5];
    const int*   db     = (const int*)d_in[6];
    const int*   ds     = (const int*)d_in[7];
    const float* dbias  = (const float*)d_in[8];
    float* out = (float*)d_out;

    build_lists_kernel<<<1, 256>>>(eidx);

    {   // qdq hidden -> bf16
        int blocks = (T * G + 7) / 8;
        qdq_hidden_kernel<<<blocks, 256>>>(hidden);
    }
    {   // GEMM1 + swiglu (tensor cores)
        dim3 grid(R1 / BN, NA / BM, NEXP);   // (90, 16, 8)
        gemm_mma_kernel<true><<<grid, 256>>>(gub, gus, gubias, R1);
    }
    {   // qdq activations -> bf16
        int blocks = (NA * G + 7) / 8;
        qdq_act_kernel<<<blocks, 256>>>();
    }
    {   // GEMM2 (tensor cores)
        dim3 grid(H / BN, NA / BM, NEXP);    // (45, 16, 8)
        gemm_mma_kernel<false><<<grid, 256>>>(db, ds, dbias, H);
    }
    combine_kernel<<<T, 256>>>(rw, out);
}

// round 11
// speedup vs baseline: 1.3539x; 1.3539x over previous
#include <cuda_runtime.h>
#include <cuda_bf16.h>
#include <cuda_fp8.h>
#include <cuda_fp16.h>
#include <math.h>
#include <stdint.h>

// Problem shape (fixed)
#define T 1024
#define H 2880
#define NI 2880
#define NEXP 8
#define R1 5760          // 2*I rows of gate_up
#define G 90             // K groups of 32
#define NA 2048          // T * topk

// GEMM tile
#define BM 128
#define BN 64
#define ASTR 40          // padded row stride in bf16 elems (80 bytes)
#define ASTRB 80
#define STAGE_ELEMS ((BM + BN) * ASTR)     // 7680 bf16 per stage
#define BS_OFF (BM * ASTR)                 // Bs offset within stage (elems)

// ---------------- scratch ---------------------------------------------------
__device__ __nv_bfloat16 g_xq[T * H];      // qdq'd hidden, bf16 (exact)
__device__ float         g_act[NA * NI];   // swiglu activations fp32
__device__ __nv_bfloat16 g_actb[NA * NI];  // qdq'd activations, bf16 (exact)
__device__ float         g_out2[NA * H];   // per-assignment outputs
__device__ int g_tok[NA], g_pair_row[NA], g_cnt[NEXP], g_off[NEXP];

// ---------------- expert grouping (deterministic) ---------------------------
__global__ void build_lists_kernel(const int* __restrict__ eidx) {
    __shared__ int se[NA];
    __shared__ int offs[NEXP];
    int tid = threadIdx.x;
    for (int i = tid; i < NA; i += 256) se[i] = eidx[i];
    __syncthreads();
    if (tid < NEXP) {
        int c = 0;
        for (int i = 0; i < NA; i++) c += (se[i] == tid);
        g_cnt[tid] = c;
    }
    __syncthreads();
    if (tid == 0) {
        int s = 0;
        for (int e = 0; e < NEXP; e++) { offs[e] = s; g_off[e] = s; s += g_cnt[e]; }
    }
    __syncthreads();
    if (tid < NEXP) {
        int pos = offs[tid];
        for (int i = 0; i < NA; i++) {
            if (se[i] == tid) {
                g_tok[pos] = i >> 1;
                g_pair_row[i] = pos;
                pos++;
            }
        }
    }
}

// ---------------- MXFP8 qdq -> bf16 -----------------------------------------
__device__ __forceinline__ void qdq_block_bf16(const float* __restrict__ in,
                                               __nv_bfloat16* __restrict__ out,
                                               int nblk) {
    int w = (blockIdx.x * blockDim.x + threadIdx.x) >> 5;
    int lane = threadIdx.x & 31;
    if (w >= nblk) return;
    size_t idx = (size_t)w * 32 + lane;
    float v = in[idx];
    float a = fabsf(v);
#pragma unroll
    for (int o = 16; o; o >>= 1) a = fmaxf(a, __shfl_xor_sync(0xffffffffu, a, o));
    a = fmaxf(a, 1e-12f);
    int k; float m = frexpf(a, &k);
    int ee = (m == 0.5f) ? (k - 1) : k;     // exact ceil(log2(a))
    ee = max(-127, min(128, ee));
    float inv = ldexpf(1.0f, -ee);
    float scale = ldexpf(1.0f, ee);
    __nv_fp8_storage_t q = __nv_cvt_float_to_fp8(v * inv, __NV_SATFINITE, __NV_E4M3);
    __half_raw hr = __nv_cvt_fp8_to_halfraw(q, __NV_E4M3);
    float deq = __half2float(*(__half*)&hr);
    out[idx] = __float2bfloat16(deq * scale);   // exact: 3-bit mantissa * 2^e
}

__global__ void qdq_hidden_kernel(const float* __restrict__ hidden) {
    qdq_block_bf16(hidden, g_xq, T * G);
}
__global__ void qdq_act_kernel() {
    qdq_block_bf16(g_act, g_actb, NA * G);
}

// ---------------- low-level helpers -----------------------------------------
__device__ __forceinline__ void ldsm_x4(uint32_t* r, uint32_t addr) {
    asm volatile("ldmatrix.sync.aligned.m8n8.x4.shared.b16 {%0,%1,%2,%3}, [%4];\n"
                 : "=r"(r[0]), "=r"(r[1]), "=r"(r[2]), "=r"(r[3]) : "r"(addr));
}
__device__ __forceinline__ void mma16816(float* d, const uint32_t* a,
                                         uint32_t b0, uint32_t b1) {
    asm volatile(
        "mma.sync.aligned.m16n8k16.row.col.f32.bf16.bf16.f32 "
        "{%0,%1,%2,%3}, {%4,%5,%6,%7}, {%8,%9}, {%0,%1,%2,%3};\n"
        : "+f"(d[0]), "+f"(d[1]), "+f"(d[2]), "+f"(d[3])
        : "r"(a[0]), "r"(a[1]), "r"(a[2]), "r"(a[3]), "r"(b0), "r"(b1));
}
__device__ __forceinline__ uint32_t mulbf2(uint32_t a, uint32_t b) {
    uint32_t d;
    asm("mul.rn.bf16x2 %0, %1, %2;\n" : "=r"(d) : "r"(a), "r"(b));
    return d;
}

// PRMT-based fp4 dequant (verified correct in round 10): 4 int32 (one packed
// byte each: lo/hi nibble = 2 fp4 values) + E8M0 scale -> 4 x bf16x2 in
// k-order (lo0,hi0),(lo1,hi1),...  Exact in bf16.
__device__ __forceinline__ void dequant8(int4 v, int sval, uint32_t* out) {
    uint32_t c1 = __byte_perm((uint32_t)v.x, (uint32_t)v.y, 0x0040);
    uint32_t c2 = __byte_perm((uint32_t)v.z, (uint32_t)v.w, 0x4000);
    uint32_t comb = __byte_perm(c1, c2, 0x7610);   // [b(x),b(y),b(z),b(w)]
    uint32_t chn = comb >> 4;
    uint32_t xl = comb & 0x07070707u;              // lo-nibble codes (bytes)
    uint32_t xh = chn & 0x07070707u;               // hi-nibble codes (bytes)
    uint32_t sgl = (comb & 0x08080808u) << 4;      // sign -> bf16 bit15 byte
    uint32_t sgh = (chn & 0x08080808u) << 4;
    uint32_t yl = xl | (xl >> 4);                  // b0=c0|c1<<4, b2=c2|c3<<4
    uint32_t yh = xh | (xh >> 4);
    uint32_t sel_l = __byte_perm(yl, yl, 0x0020);  // sel nibbles = c0,c1,c2,c3
    uint32_t sel_h = __byte_perm(yh, yh, 0x0020);
    // bf16 magnitude byte tables for fp4 codes 0..7: {0,.5,1,1.5,2,3,4,6}
    uint32_t hbLo = __byte_perm(0x3F3F3F00u, 0x40404040u, sel_l) | sgl;
    uint32_t lbLo = __byte_perm(0xC0800000u, 0xC0804000u, sel_l);
    uint32_t hbHi = __byte_perm(0x3F3F3F00u, 0x40404040u, sel_h) | sgh;
    uint32_t lbHi = __byte_perm(0xC0800000u, 0xC0804000u, sel_h);
    uint32_t M0 = __byte_perm(lbLo, hbLo, 0x5140);  // bf16(lo0)|bf16(lo1)<<16
    uint32_t M1 = __byte_perm(lbLo, hbLo, 0x7362);
    uint32_t N0 = __byte_perm(lbHi, hbHi, 0x5140);
    uint32_t N1 = __byte_perm(lbHi, hbHi, 0x7362);
    uint32_t sb = ((uint32_t)sval) << 7;            // bf16 2^(sval-127)
    sb |= sb << 16;
    out[0] = mulbf2(__byte_perm(M0, N0, 0x5410), sb);
    out[1] = mulbf2(__byte_perm(M0, N0, 0x7632), sb);
    out[2] = mulbf2(__byte_perm(M1, N1, 0x5410), sb);
    out[3] = mulbf2(__byte_perm(M1, N1, 0x7632), sb);
}

// ---------------- tensor-core GEMM (both stages) -----------------------------
// C[128,64] per block; 8 warps of 32x32. 2-stage smem double buffer, plain-LDG
// register prefetch (round-7 proven pattern), ONE __syncthreads per K-group,
// PRMT dequant. Store of group g+1 happens after compute of group g:
//  - readers of stage (g+1)&1 ran in iter g-1, before this iter's barrier.
//  - LDG for g+1 issued at top of iter g -> one full compute phase of latency.
template <bool IS_G1>
__global__ __launch_bounds__(256, 2) void gemm_mma_kernel(
    const int* __restrict__ wblocks, const int* __restrict__ wscales,
    const float* __restrict__ wbias, int NR) {
    int e = blockIdx.z;
    int cnt = g_cnt[e];
    int m0 = blockIdx.y * BM;
    if (m0 >= cnt) return;
    int off = g_off[e];
    int nt = blockIdx.x;

    __shared__ __nv_bfloat16 ring[2 * STAGE_ELEMS];   // 30 KB
    int tid = threadIdx.x;

    // --- A mapping: 2 threads per row, 32B (16 bf16) each ---
    int a_m = tid >> 1;
    int a_half = tid & 1;
    int arow = min(m0 + a_m, cnt - 1);   // clamp; garbage rows never stored out
    const __nv_bfloat16* aptr;
    if (IS_G1) {
        int tok = g_tok[off + arow];
        aptr = g_xq + (size_t)tok * H + a_half * 16;
    } else {
        aptr = g_actb + (size_t)(off + arow) * NI + a_half * 16;
    }
    // --- B mapping: 4 threads per weight row, 4 int32 (8 fp4 values) ---
    int b_n = tid >> 2;
    int b_i = tid & 3;
    int wrow = e * NR + nt * BN + b_n;
    const int* bptr = wblocks + (size_t)wrow * (G * 16) + b_i * 4;
    const int* sptr = wscales + (size_t)wrow * G;

    uint32_t ring_u = (uint32_t)__cvta_generic_to_shared(ring);
    uint32_t st_u[2] = {ring_u, ring_u + STAGE_ELEMS * 2};
    uint32_t a_dst_off = (uint32_t)a_m * ASTRB + a_half * 32;   // bytes
    uint32_t b_dst_off = BS_OFF * 2 + (uint32_t)b_n * ASTRB + b_i * 16;

    // per-warp ldmatrix offsets (within a stage)
    int wid = tid >> 5, lane = tid & 31;
    int wm = (wid & 3) * 32;
    int wn = (wid >> 2) * 32;
    uint32_t aA_off = (uint32_t)(wm + (lane & 15)) * ASTRB + (lane >> 4) * 16;
    uint32_t aB_off = BS_OFF * 2 + (uint32_t)(wn + (lane & 15)) * ASTRB +
                      (lane >> 4) * 16;

    float acc[2][4][4];
#pragma unroll
    for (int i = 0; i < 2; i++)
#pragma unroll
        for (int j = 0; j < 4; j++)
#pragma unroll
            for (int c = 0; c < 4; c++) acc[i][j][c] = 0.0f;

    // ---- prologue: load + store group 0 into stage 0 ----
    {
        uint4 a0 = *(const uint4*)(aptr);
        uint4 a1 = *(const uint4*)(aptr + 8);
        int4  bv = *(const int4*)(bptr);
        int   sv = sptr[0];
        uint32_t d = st_u[0] + a_dst_off;
        asm volatile("st.shared.v4.b32 [%0], {%1,%2,%3,%4};\n"
                     :: "r"(d), "r"(a0.x), "r"(a0.y), "r"(a0.z), "r"(a0.w));
        asm volatile("st.shared.v4.b32 [%0], {%1,%2,%3,%4};\n"
                     :: "r"(d + 16), "r"(a1.x), "r"(a1.y), "r"(a1.z), "r"(a1.w));
        uint32_t o[4];
        dequant8(bv, sv, o);
        asm volatile("st.shared.v4.b32 [%0], {%1,%2,%3,%4};\n"
                     :: "r"(st_u[0] + b_dst_off),
                        "r"(o[0]), "r"(o[1]), "r"(o[2]), "r"(o[3]));
    }

    for (int g = 0; g < G; ++g) {
        // issue next group's global loads first (covered by compute below)
        uint4 a0n, a1n; int4 bvn; int svn = 0;
        bool have_next = (g + 1 < G);
        if (have_next) {
            const __nv_bfloat16* ap = aptr + (size_t)(g + 1) * 32;
            a0n = *(const uint4*)(ap);
            a1n = *(const uint4*)(ap + 8);
            bvn = *(const int4*)(bptr + (size_t)(g + 1) * 16);
            svn = sptr[g + 1];
        }
        __syncthreads();   // stage g&1 stores (iter g-1 / prologue) visible
        // compute group g from stage g&1
        uint32_t aA = st_u[g & 1] + aA_off;
        uint32_t aB = st_u[g & 1] + aB_off;
#pragma unroll
        for (int ss = 0; ss < 2; ss++) {
            uint32_t A0[4], A1[4], B0[4], B1[4];
            ldsm_x4(A0, aA + ss * 32);
            ldsm_x4(A1, aA + 16 * ASTRB + ss * 32);
            ldsm_x4(B0, aB + ss * 32);
            ldsm_x4(B1, aB + 16 * ASTRB + ss * 32);
            mma16816(acc[0][0], A0, B0[0], B0[2]);
            mma16816(acc[0][1], A0, B0[1], B0[3]);
            mma16816(acc[0][2], A0, B1[0], B1[2]);
            mma16816(acc[0][3], A0, B1[1], B1[3]);
            mma16816(acc[1][0], A1, B0[0], B0[2]);
            mma16816(acc[1][1], A1, B0[1], B0[3]);
            mma16816(acc[1][2], A1, B1[0], B1[2]);
            mma16816(acc[1][3], A1, B1[1], B1[3]);
        }
        // store group g+1 into stage (g+1)&1 (its readers finished in iter g-1,
        // strictly before this iteration's barrier)
        if (have_next) {
            uint32_t d = st_u[(g + 1) & 1] + a_dst_off;
            asm volatile("st.shared.v4.b32 [%0], {%1,%2,%3,%4};\n"
                         :: "r"(d), "r"(a0n.x), "r"(a0n.y), "r"(a0n.z), "r"(a0n.w));
            asm volatile("st.shared.v4.b32 [%0], {%1,%2,%3,%4};\n"
                         :: "r"(d + 16), "r"(a1n.x), "r"(a1n.y), "r"(a1n.z), "r"(a1n.w));
            uint32_t o[4];
            dequant8(bvn, svn, o);
            asm volatile("st.shared.v4.b32 [%0], {%1,%2,%3,%4};\n"
                         :: "r"(st_u[(g + 1) & 1] + b_dst_off),
                            "r"(o[0]), "r"(o[1]), "r"(o[2]), "r"(o[3]));
        }
    }

    // ---------------- epilogue ----------------
    int lm = lane >> 2;
    int lc = (lane & 3) * 2;
#pragma unroll
    for (int ms = 0; ms < 2; ms++) {
#pragma unroll
        for (int nf = 0; nf < 4; nf++) {
            int col = nt * BN + wn + nf * 8 + lc;
            int rbase = m0 + wm + ms * 16 + lm;
            float c0 = acc[ms][nf][0], c1 = acc[ms][nf][1];
            float c2 = acc[ms][nf][2], c3 = acc[ms][nf][3];
            if (IS_G1) {
                float be = wbias[e * R1 + col];
                float bo = wbias[e * R1 + col + 1];
                int j = col >> 1;
                if (rbase < cnt) {
                    float gate = fminf(c0 + be, 7.0f);
                    float up = fminf(fmaxf(c1 + bo, -7.0f), 7.0f);
                    float glu = gate / (1.0f + expf(-1.702f * gate));
                    g_act[(size_t)(off + rbase) * NI + j] = (up + 1.0f) * glu;
                }
                if (rbase + 8 < cnt) {
                    float gate = fminf(c2 + be, 7.0f);
                    float up = fminf(fmaxf(c3 + bo, -7.0f), 7.0f);
                    float glu = gate / (1.0f + expf(-1.702f * gate));
                    g_act[(size_t)(off + rbase + 8) * NI + j] = (up + 1.0f) * glu;
                }
            } else {
                float b0 = wbias[e * H + col];
                float b1 = wbias[e * H + col + 1];
                if (rbase < cnt) {
                    float2 r = make_float2(c0 + b0, c1 + b1);
                    *(float2*)(g_out2 + (size_t)(off + rbase) * H + col) = r;
                }
                if (rbase + 8 < cnt) {
                    float2 r = make_float2(c2 + b0, c3 + b1);
                    *(float2*)(g_out2 + (size_t)(off + rbase + 8) * H + col) = r;
                }
            }
        }
    }
}

// ---------------- combine (deterministic) -----------------------------------
__global__ void combine_kernel(const float* __restrict__ rw,
                               float* __restrict__ out) {
    int t = blockIdx.x;
    int r0 = g_pair_row[t * 2 + 0];
    int r1 = g_pair_row[t * 2 + 1];
    float w0 = rw[t * 2 + 0];
    float w1 = rw[t * 2 + 1];
    const float* p0 = g_out2 + (size_t)r0 * H;
    const float* p1 = g_out2 + (size_t)r1 * H;
    float* po = out + (size_t)t * H;
    for (int n = threadIdx.x; n < H; n += blockDim.x)
        po[n] = w0 * p0[n] + w1 * p1[n];
}

// ---------------- launch ------------------------------------------------------
extern "C" void kernel_launch(void* const* d_in, const int* in_sizes, int n_in,
                              void* d_out, int out_size) {
    const float* hidden = (const float*)d_in[0];
    const int*   eidx   = (const int*)d_in[1];
    const float* rw     = (const float*)d_in[2];
    const int*   gub    = (const int*)d_in[3];
    const int*   gus    = (const int*)d_in[4];
    const float* gubias = (const float*)d_in[5];
    const int*   db     = (const int*)d_in[6];
    const int*   ds     = (const int*)d_in[7];
    const float* dbias  = (const float*)d_in[8];
    float* out = (float*)d_out;

    build_lists_kernel<<<1, 256>>>(eidx);

    {   // qdq hidden -> bf16
        int blocks = (T * G + 7) / 8;
        qdq_hidden_kernel<<<blocks, 256>>>(hidden);
    }
    {   // GEMM1 + swiglu (tensor cores)
        dim3 grid(R1 / BN, NA / BM, NEXP);   // (90, 16, 8)
        gemm_mma_kernel<true><<<grid, 256>>>(gub, gus, gubias, R1);
    }
    {   // qdq activations -> bf16
        int blocks = (NA * G + 7) / 8;
        qdq_act_kernel<<<blocks, 256>>>();
    }
    {   // GEMM2 (tensor cores)
        dim3 grid(H / BN, NA / BM, NEXP);    // (45, 16, 8)
        gemm_mma_kernel<false><<<grid, 256>>>(db, ds, dbias, H);
    }
    combine_kernel<<<T, 256>>>(rw, out);
}

// round 13
// speedup vs baseline: 1.5369x; 1.1352x over previous
#include <cuda_runtime.h>
#include <cuda_bf16.h>
#include <cuda_fp8.h>
#include <cuda_fp16.h>
#include <math.h>
#include <stdint.h>

// Problem shape (fixed)
#define T 1024
#define H 2880
#define NI 2880
#define NEXP 8
#define R1 5760          // 2*I rows of gate_up
#define G 90             // K groups of 32
#define NA 2048          // T * topk

// GEMM tile: C[128,64], K-step 64 (two fp4 groups) per iteration
#define BM 128
#define BN 64
#define BK 64
#define CHUNKS 45                    // 2880 / 64
#define ASTRB 144                    // padded row stride bytes (64 bf16 + 16B pad)
#define A_BYTES (BM * ASTRB)         // 18432
#define B_BYTES (BN * ASTRB)         // 9216
#define STAGE_B (A_BYTES + B_BYTES)  // 27648
#define SMEM_DYN (1024 + 2 * STAGE_B)

// ---------------- scratch ---------------------------------------------------
__device__ __nv_bfloat16 g_xq[T * H];      // qdq'd hidden, bf16 (exact)
__device__ __nv_bfloat16 g_actb[NA * NI];  // qdq'd activations, bf16 (exact)
__device__ float         g_out2[NA * H];   // per-assignment outputs
__device__ int g_tok[NA], g_pair_row[NA], g_cnt[NEXP], g_off[NEXP];

// ---------------- expert grouping (deterministic) ---------------------------
__global__ void build_lists_kernel(const int* __restrict__ eidx) {
    __shared__ int se[NA];
    __shared__ int offs[NEXP];
    int tid = threadIdx.x;
    for (int i = tid; i < NA; i += 256) se[i] = eidx[i];
    __syncthreads();
    if (tid < NEXP) {
        int c = 0;
        for (int i = 0; i < NA; i++) c += (se[i] == tid);
        g_cnt[tid] = c;
    }
    __syncthreads();
    if (tid == 0) {
        int s = 0;
        for (int e = 0; e < NEXP; e++) { offs[e] = s; g_off[e] = s; s += g_cnt[e]; }
    }
    __syncthreads();
    if (tid < NEXP) {
        int pos = offs[tid];
        for (int i = 0; i < NA; i++) {
            if (se[i] == tid) {
                g_tok[pos] = i >> 1;
                g_pair_row[i] = pos;
                pos++;
            }
        }
    }
}

// ---------------- MXFP8 qdq helpers ------------------------------------------
__device__ __forceinline__ int ceil_log2(float a) {
    int k; float m = frexpf(a, &k);
    int ee = (m == 0.5f) ? (k - 1) : k;   // exact ceil(log2(a))
    return max(-127, min(128, ee));
}
__device__ __forceinline__ float qdq_one(float v, float inv, float scale) {
    __nv_fp8_storage_t q = __nv_cvt_float_to_fp8(v * inv, __NV_SATFINITE, __NV_E4M3);
    __half_raw hr = __nv_cvt_fp8_to_halfraw(q, __NV_E4M3);
    return __half2float(*(__half*)&hr) * scale;
}

// Vectorized hidden qdq: 8 values/thread, 4 threads per 32-block.
__global__ void qdq_hidden_kernel(const float* __restrict__ in) {
    int gid = blockIdx.x * blockDim.x + threadIdx.x;   // T*H/8 threads
    size_t idx = (size_t)gid * 8;
    float4 v0 = *(const float4*)(in + idx);
    float4 v1 = *(const float4*)(in + idx + 4);
    float f[8] = {v0.x, v0.y, v0.z, v0.w, v1.x, v1.y, v1.z, v1.w};
    float a = 0.0f;
#pragma unroll
    for (int j = 0; j < 8; j++) a = fmaxf(a, fabsf(f[j]));
    a = fmaxf(a, __shfl_xor_sync(0xffffffffu, a, 1));
    a = fmaxf(a, __shfl_xor_sync(0xffffffffu, a, 2));
    a = fmaxf(a, 1e-12f);
    int ee = ceil_log2(a);
    float inv = ldexpf(1.0f, -ee);
    float scale = ldexpf(1.0f, ee);
    __nv_bfloat16 o[8];
#pragma unroll
    for (int j = 0; j < 8; j++) o[j] = __float2bfloat16(qdq_one(f[j], inv, scale));
    *(uint4*)(g_xq + idx) = *(uint4*)o;
}

// ---------------- low-level helpers -----------------------------------------
__device__ __forceinline__ void ldsm_x4(uint32_t* r, uint32_t addr) {
    asm volatile("ldmatrix.sync.aligned.m8n8.x4.shared.b16 {%0,%1,%2,%3}, [%4];\n"
                 : "=r"(r[0]), "=r"(r[1]), "=r"(r[2]), "=r"(r[3]) : "r"(addr));
}
__device__ __forceinline__ void mma16816(float* d, const uint32_t* a,
                                         uint32_t b0, uint32_t b1) {
    asm volatile(
        "mma.sync.aligned.m16n8k16.row.col.f32.bf16.bf16.f32 "
        "{%0,%1,%2,%3}, {%4,%5,%6,%7}, {%8,%9}, {%0,%1,%2,%3};\n"
        : "+f"(d[0]), "+f"(d[1]), "+f"(d[2]), "+f"(d[3])
        : "r"(a[0]), "r"(a[1]), "r"(a[2]), "r"(a[3]), "r"(b0), "r"(b1));
}
__device__ __forceinline__ uint32_t mulbf2(uint32_t a, uint32_t b) {
    uint32_t d;
    asm("mul.rn.bf16x2 %0, %1, %2;\n" : "=r"(d) : "r"(a), "r"(b));
    return d;
}

// PRMT-based fp4 dequant (verified R10/R11): 4 int32 (one packed byte each) +
// E8M0 scale -> 4 x bf16x2 in k-order (lo0,hi0),(lo1,hi1),...  Exact in bf16.
__device__ __forceinline__ void dequant8(int4 v, int sval, uint32_t* out) {
    uint32_t c1 = __byte_perm((uint32_t)v.x, (uint32_t)v.y, 0x0040);
    uint32_t c2 = __byte_perm((uint32_t)v.z, (uint32_t)v.w, 0x4000);
    uint32_t comb = __byte_perm(c1, c2, 0x7610);   // [b(x),b(y),b(z),b(w)]
    uint32_t chn = comb >> 4;
    uint32_t xl = comb & 0x07070707u;
    uint32_t xh = chn & 0x07070707u;
    uint32_t sgl = (comb & 0x08080808u) << 4;
    uint32_t sgh = (chn & 0x08080808u) << 4;
    uint32_t yl = xl | (xl >> 4);
    uint32_t yh = xh | (xh >> 4);
    uint32_t sel_l = __byte_perm(yl, yl, 0x0020);
    uint32_t sel_h = __byte_perm(yh, yh, 0x0020);
    uint32_t hbLo = __byte_perm(0x3F3F3F00u, 0x40404040u, sel_l) | sgl;
    uint32_t lbLo = __byte_perm(0xC0800000u, 0xC0804000u, sel_l);
    uint32_t hbHi = __byte_perm(0x3F3F3F00u, 0x40404040u, sel_h) | sgh;
    uint32_t lbHi = __byte_perm(0xC0800000u, 0xC0804000u, sel_h);
    uint32_t M0 = __byte_perm(lbLo, hbLo, 0x5140);
    uint32_t M1 = __byte_perm(lbLo, hbLo, 0x7362);
    uint32_t N0 = __byte_perm(lbHi, hbHi, 0x5140);
    uint32_t N1 = __byte_perm(lbHi, hbHi, 0x7362);
    uint32_t sb = ((uint32_t)sval) << 7;
    sb |= sb << 16;
    out[0] = mulbf2(__byte_perm(M0, N0, 0x5410), sb);
    out[1] = mulbf2(__byte_perm(M0, N0, 0x7632), sb);
    out[2] = mulbf2(__byte_perm(M1, N1, 0x5410), sb);
    out[3] = mulbf2(__byte_perm(M1, N1, 0x7632), sb);
}

// ---------------- tensor-core GEMM (both stages) -----------------------------
// C[128,64] per block; 8 warps of 32x32; K loop over 45 chunks of 64.
// 2-stage smem double buffer (pad-stride 144B), LDG register prefetch, ONE
// __syncthreads per chunk. GEMM1 fuses swiglu + act MXFP8-qdq -> g_actb.
template <bool IS_G1>
__global__ __launch_bounds__(256, 2) void gemm_mma_kernel(
    const int* __restrict__ wblocks, const int* __restrict__ wscales,
    const float* __restrict__ wbias, int NR) {
    extern __shared__ char dsmem[];
    int e = blockIdx.z;
    int cnt = g_cnt[e];
    int m0 = blockIdx.y * BM;
    if (m0 >= cnt) return;
    int off = g_off[e];
    int nt = blockIdx.x;
    int tid = threadIdx.x;

    uint32_t sbase = (uint32_t)__cvta_generic_to_shared(dsmem);
    uint32_t abase = (sbase + 1023) & ~1023u;
    uint32_t st_u[2] = {abase, abase + STAGE_B};

    // --- A mapping: 2 threads per row, 64B (32 bf16) each ---
    int a_m = tid >> 1;
    int a_half = tid & 1;
    int arow = min(m0 + a_m, cnt - 1);   // clamp; garbage rows never stored out
    const __nv_bfloat16* aptr;
    if (IS_G1) {
        aptr = g_xq + (size_t)g_tok[off + arow] * H + a_half * 32;
    } else {
        aptr = g_actb + (size_t)(off + arow) * NI + a_half * 32;
    }
    // --- B mapping: 4 threads per weight row; per chunk 2 groups x int4 ---
    int b_n = tid >> 2;
    int b_i = tid & 3;
    size_t wrow = (size_t)(e * NR + nt * BN + b_n);
    const int* bptr = wblocks + wrow * (G * 16) + b_i * 4;
    const int* sptr = wscales + wrow * G;

    uint32_t a_dst = (uint32_t)a_m * ASTRB + a_half * 64;            // bytes
    uint32_t b_dst = A_BYTES + (uint32_t)b_n * ASTRB + b_i * 16;

    // per-warp ldmatrix offsets (within a stage)
    int wid = tid >> 5, lane = tid & 31;
    int wm = (wid & 3) * 32;
    int wn = (wid >> 2) * 32;
    uint32_t aA_off = (uint32_t)(wm + (lane & 15)) * ASTRB + (lane >> 4) * 16;
    uint32_t aB_off = A_BYTES + (uint32_t)(wn + (lane & 15)) * ASTRB +
                      (lane >> 4) * 16;

    float acc[2][4][4];
#pragma unroll
    for (int i = 0; i < 2; i++)
#pragma unroll
        for (int j = 0; j < 4; j++)
#pragma unroll
            for (int c = 0; c < 4; c++) acc[i][j][c] = 0.0f;

    // ---- prologue: load + store chunk 0 into stage 0 ----
    {
        uint4 av[4];
#pragma unroll
        for (int j = 0; j < 4; j++) av[j] = *(const uint4*)(aptr + j * 8);
        int4 bv0 = *(const int4*)(bptr);
        int4 bv1 = *(const int4*)(bptr + 16);
        int sv0 = sptr[0], sv1 = sptr[1];
        uint32_t d = st_u[0] + a_dst;
#pragma unroll
        for (int j = 0; j < 4; j++)
            asm volatile("st.shared.v4.b32 [%0], {%1,%2,%3,%4};"
                         :: "r"(d + j * 16),
                            "r"(av[j].x), "r"(av[j].y), "r"(av[j].z), "r"(av[j].w));
        uint32_t o[4];
        dequant8(bv0, sv0, o);
        asm volatile("st.shared.v4.b32 [%0], {%1,%2,%3,%4};"
                     :: "r"(st_u[0] + b_dst), "r"(o[0]), "r"(o[1]), "r"(o[2]), "r"(o[3]));
        dequant8(bv1, sv1, o);
        asm volatile("st.shared.v4.b32 [%0], {%1,%2,%3,%4};"
                     :: "r"(st_u[0] + b_dst + 64), "r"(o[0]), "r"(o[1]), "r"(o[2]), "r"(o[3]));
    }

    for (int c = 0; c < CHUNKS; ++c) {
        // issue next chunk's global loads first (covered by compute below)
        uint4 avn[4]; int4 bv0n, bv1n; int sv0n = 0, sv1n = 0;
        bool have_next = (c + 1 < CHUNKS);
        if (have_next) {
            const __nv_bfloat16* ap = aptr + (size_t)(c + 1) * BK;
#pragma unroll
            for (int j = 0; j < 4; j++) avn[j] = *(const uint4*)(ap + j * 8);
            bv0n = *(const int4*)(bptr + (size_t)(2 * c + 2) * 16);
            bv1n = *(const int4*)(bptr + (size_t)(2 * c + 3) * 16);
            sv0n = sptr[2 * c + 2];
            sv1n = sptr[2 * c + 3];
        }
        __syncthreads();   // stage c&1 stores (iter c-1 / prologue) visible
        // compute chunk c from stage c&1 (4 K16 steps, 32 HMMA)
        uint32_t aA = st_u[c & 1] + aA_off;
        uint32_t aB = st_u[c & 1] + aB_off;
#pragma unroll
        for (int ss = 0; ss < 4; ss++) {
            uint32_t A0[4], A1[4], B0[4], B1[4];
            ldsm_x4(A0, aA + ss * 32);
            ldsm_x4(A1, aA + 16 * ASTRB + ss * 32);
            ldsm_x4(B0, aB + ss * 32);
            ldsm_x4(B1, aB + 16 * ASTRB + ss * 32);
            mma16816(acc[0][0], A0, B0[0], B0[2]);
            mma16816(acc[0][1], A0, B0[1], B0[3]);
            mma16816(acc[0][2], A0, B1[0], B1[2]);
            mma16816(acc[0][3], A0, B1[1], B1[3]);
            mma16816(acc[1][0], A1, B0[0], B0[2]);
            mma16816(acc[1][1], A1, B0[1], B0[3]);
            mma16816(acc[1][2], A1, B1[0], B1[2]);
            mma16816(acc[1][3], A1, B1[1], B1[3]);
        }
        // store chunk c+1 into stage (c+1)&1 (readers finished in iter c-1)
        if (have_next) {
            uint32_t d = st_u[(c + 1) & 1] + a_dst;
#pragma unroll
            for (int j = 0; j < 4; j++)
                asm volatile("st.shared.v4.b32 [%0], {%1,%2,%3,%4};"
                             :: "r"(d + j * 16),
                                "r"(avn[j].x), "r"(avn[j].y), "r"(avn[j].z), "r"(avn[j].w));
            uint32_t o[4];
            dequant8(bv0n, sv0n, o);
            asm volatile("st.shared.v4.b32 [%0], {%1,%2,%3,%4};"
                         :: "r"(st_u[(c + 1) & 1] + b_dst),
                            "r"(o[0]), "r"(o[1]), "r"(o[2]), "r"(o[3]));
            dequant8(bv1n, sv1n, o);
            asm volatile("st.shared.v4.b32 [%0], {%1,%2,%3,%4};"
                         :: "r"(st_u[(c + 1) & 1] + b_dst + 64),
                            "r"(o[0]), "r"(o[1]), "r"(o[2]), "r"(o[3]));
        }
    }

    // ---------------- epilogue ----------------
    int lm = lane >> 2;
    int lc = (lane & 3) * 2;
    if (IS_G1) {
        // swiglu -> fp32 act values, then fused MXFP8 qdq -> bf16 g_actb.
        // One GEMM1 block covers exactly one 32-wide qdq block per row.
        float av[2][2][4];             // [ms][rowpair][nf]
        float rmax[2][2] = {{0.f, 0.f}, {0.f, 0.f}};
#pragma unroll
        for (int ms = 0; ms < 2; ms++) {
#pragma unroll
            for (int nf = 0; nf < 4; nf++) {
                int col = nt * BN + wn + nf * 8 + lc;
                float be = wbias[e * R1 + col];
                float bo = wbias[e * R1 + col + 1];
                {
                    float gate = fminf(acc[ms][nf][0] + be, 7.0f);
                    float up = fminf(fmaxf(acc[ms][nf][1] + bo, -7.0f), 7.0f);
                    float glu = gate / (1.0f + expf(-1.702f * gate));
                    float a0 = (up + 1.0f) * glu;
                    av[ms][0][nf] = a0;
                    rmax[ms][0] = fmaxf(rmax[ms][0], fabsf(a0));
                }
                {
                    float gate = fminf(acc[ms][nf][2] + be, 7.0f);
                    float up = fminf(fmaxf(acc[ms][nf][3] + bo, -7.0f), 7.0f);
                    float glu = gate / (1.0f + expf(-1.702f * gate));
                    float a1 = (up + 1.0f) * glu;
                    av[ms][1][nf] = a1;
                    rmax[ms][1] = fmaxf(rmax[ms][1], fabsf(a1));
                }
            }
        }
        // reduce over the 4-lane column group (lanes differ in bits 0-1)
#pragma unroll
        for (int ms = 0; ms < 2; ms++)
#pragma unroll
            for (int p = 0; p < 2; p++) {
                rmax[ms][p] = fmaxf(rmax[ms][p],
                                    __shfl_xor_sync(0xffffffffu, rmax[ms][p], 1));
                rmax[ms][p] = fmaxf(rmax[ms][p],
                                    __shfl_xor_sync(0xffffffffu, rmax[ms][p], 2));
            }
        // cross-warp (two n-halves) exchange via smem
        __syncthreads();                      // ring reads done; reuse as float buf
        float* smax = (float*)dsmem;
        int half = wid >> 2;
        if ((lane & 3) == 0) {
#pragma unroll
            for (int ms = 0; ms < 2; ms++)
#pragma unroll
                for (int p = 0; p < 2; p++)
                    smax[half * 128 + wm + ms * 16 + p * 8 + lm] = rmax[ms][p];
        }
        __syncthreads();
#pragma unroll
        for (int ms = 0; ms < 2; ms++) {
#pragma unroll
            for (int p = 0; p < 2; p++) {
                int rloc = wm + ms * 16 + p * 8 + lm;
                int rbase = m0 + rloc;
                float bm = fmaxf(fmaxf(rmax[ms][p], smax[(1 ^ half) * 128 + rloc]),
                                 1e-12f);
                int ee = ceil_log2(bm);
                float inv = ldexpf(1.0f, -ee);
                float scale = ldexpf(1.0f, ee);
                if (rbase < cnt) {
                    __nv_bfloat16* dst = g_actb + (size_t)(off + rbase) * NI +
                                         nt * 32 + (wn >> 1) + (lane & 3);
#pragma unroll
                    for (int nf = 0; nf < 4; nf++)
                        dst[nf * 4] = __float2bfloat16(qdq_one(av[ms][p][nf], inv, scale));
                }
            }
        }
    } else {
#pragma unroll
        for (int ms = 0; ms < 2; ms++) {
#pragma unroll
            for (int nf = 0; nf < 4; nf++) {
                int col = nt * BN + wn + nf * 8 + lc;
                int rbase = m0 + wm + ms * 16 + lm;
                float b0 = wbias[e * H + col];
                float b1 = wbias[e * H + col + 1];
                if (rbase < cnt) {
                    float2 r = make_float2(acc[ms][nf][0] + b0, acc[ms][nf][1] + b1);
                    *(float2*)(g_out2 + (size_t)(off + rbase) * H + col) = r;
                }
                if (rbase + 8 < cnt) {
                    float2 r = make_float2(acc[ms][nf][2] + b0, acc[ms][nf][3] + b1);
                    *(float2*)(g_out2 + (size_t)(off + rbase + 8) * H + col) = r;
                }
            }
        }
    }
}

// ---------------- combine (deterministic) -----------------------------------
__global__ void combine_kernel(const float* __restrict__ rw,
                               float* __restrict__ out) {
    int t = blockIdx.x;
    int r0 = g_pair_row[t * 2 + 0];
    int r1 = g_pair_row[t * 2 + 1];
    float w0 = rw[t * 2 + 0];
    float w1 = rw[t * 2 + 1];
    const float* p0 = g_out2 + (size_t)r0 * H;
    const float* p1 = g_out2 + (size_t)r1 * H;
    float* po = out + (size_t)t * H;
    for (int n = threadIdx.x; n < H; n += blockDim.x)
        po[n] = w0 * p0[n] + w1 * p1[n];
}

// ---------------- launch ------------------------------------------------------
extern "C" void kernel_launch(void* const* d_in, const int* in_sizes, int n_in,
                              void* d_out, int out_size) {
    const float* hidden = (const float*)d_in[0];
    const int*   eidx   = (const int*)d_in[1];
    const float* rw     = (const float*)d_in[2];
    const int*   gub    = (const int*)d_in[3];
    const int*   gus    = (const int*)d_in[4];
    const float* gubias = (const float*)d_in[5];
    const int*   db     = (const int*)d_in[6];
    const int*   ds     = (const int*)d_in[7];
    const float* dbias  = (const float*)d_in[8];
    float* out = (float*)d_out;

    static bool attr_set = false;
    if (!attr_set) {
        cudaFuncSetAttribute(gemm_mma_kernel<true>,
                             cudaFuncAttributeMaxDynamicSharedMemorySize, SMEM_DYN);
        cudaFuncSetAttribute(gemm_mma_kernel<false>,
                             cudaFuncAttributeMaxDynamicSharedMemorySize, SMEM_DYN);
        attr_set = true;
    }

    build_lists_kernel<<<1, 256>>>(eidx);

    {   // qdq hidden -> bf16 (8 values/thread)
        qdq_hidden_kernel<<<(T * H / 8) / 256, 256>>>(hidden);
    }
    {   // GEMM1 + swiglu + fused act qdq (tensor cores)
        dim3 grid(R1 / BN, NA / BM, NEXP);   // (90, 16, 8)
        gemm_mma_kernel<true><<<grid, 256, SMEM_DYN>>>(gub, gus, gubias, R1);
    }
    {   // GEMM2 (tensor cores)
        dim3 grid(H / BN, NA / BM, NEXP);    // (45, 16, 8)
        gemm_mma_kernel<false><<<grid, 256, SMEM_DYN>>>(db, ds, dbias, H);
    }
    combine_kernel<<<T, 256>>>(rw, out);
}